// round 1
// baseline (speedup 1.0000x reference)
#include <cuda_runtime.h>
#include <cuda_bf16.h>
#include <math.h>

// Problem constants
#define BATCH 8
#define SEQ   4096
#define DMODEL 512
#define NSTATE 64
#define TOKENS (BATCH*SEQ)          // 32768
#define NCHUNK 16
#define CHUNK  (SEQ/NCHUNK)         // 256
#define LN_EPS 1e-3f

// ---------------- device scratch ----------------
__device__ float g_xn [ (size_t)TOKENS * DMODEL ];   // layernormed x
__device__ float g_xp [ (size_t)TOKENS * DMODEL ];   // input projection
__device__ float g_bcx[ (size_t)TOKENS * 192 ];      // [B | C | xs] concat (N=192)
__device__ float g_ch [ (size_t)TOKENS * NSTATE ];   // C * h
__device__ float g_y1 [ (size_t)TOKENS * DMODEL ];   // pre-out-proj
__device__ float g_Wcat[ DMODEL * 192 ];
__device__ float g_bcat[ 192 ];
__device__ float g_chunkend[ BATCH * NCHUNK * NSTATE ];
__device__ float g_hinit   [ BATCH * NCHUNK * NSTATE ];

// ---------------- pack W_B | W_C | W_xs ----------------
__global__ void pack_kernel(const float* __restrict__ W_xs,
                            const float* __restrict__ W_B,
                            const float* __restrict__ b_B,
                            const float* __restrict__ W_C,
                            const float* __restrict__ b_C) {
    int idx = blockIdx.x * blockDim.x + threadIdx.x;
    if (idx < DMODEL * 192) {
        int r = idx / 192, c = idx % 192;
        float v;
        if (c < 64)       v = W_B[r * 64 + c];
        else if (c < 128) v = W_C[r * 64 + (c - 64)];
        else              v = W_xs[r * 64 + (c - 128)];
        g_Wcat[idx] = v;
    }
    if (idx < 192) {
        g_bcat[idx] = (idx < 64) ? b_B[idx] : (idx < 128 ? b_C[idx - 64] : 0.0f);
    }
}

// ---------------- LayerNorm (one token per block, 128 threads, float4) ----------------
__global__ void ln_kernel(const float* __restrict__ x,
                          const float* __restrict__ gamma,
                          const float* __restrict__ beta) {
    int row = blockIdx.x;
    const float4* xr = reinterpret_cast<const float4*>(x) + (size_t)row * 128;
    int t = threadIdx.x;
    float4 v = xr[t];
    float s = v.x + v.y + v.z + v.w;
    float q = v.x*v.x + v.y*v.y + v.z*v.z + v.w*v.w;
    #pragma unroll
    for (int o = 16; o; o >>= 1) {
        s += __shfl_xor_sync(0xffffffffu, s, o);
        q += __shfl_xor_sync(0xffffffffu, q, o);
    }
    __shared__ float ss[4], qq[4];
    int w = t >> 5, l = t & 31;
    if (l == 0) { ss[w] = s; qq[w] = q; }
    __syncthreads();
    s = ss[0] + ss[1] + ss[2] + ss[3];
    q = qq[0] + qq[1] + qq[2] + qq[3];
    float mu  = s * (1.0f / DMODEL);
    float var = q * (1.0f / DMODEL) - mu * mu;
    float inv = rsqrtf(var + LN_EPS);
    float4 gv = reinterpret_cast<const float4*>(gamma)[t];
    float4 bv = reinterpret_cast<const float4*>(beta)[t];
    float4 o;
    o.x = (v.x - mu) * inv * gv.x + bv.x;
    o.y = (v.y - mu) * inv * gv.y + bv.y;
    o.z = (v.z - mu) * inv * gv.z + bv.z;
    o.w = (v.w - mu) * inv * gv.w + bv.w;
    reinterpret_cast<float4*>(g_xn)[(size_t)row * 128 + t] = o;
}

// ---------------- tiled fp32 GEMM ----------------
// C[M,N] = A[M,K] @ B[K,N] + epilogue     (all row-major, M%BM==0, N%BN==0, K%BK==0)
// EPI 0: + bias[col]
// EPI 1: + bias[col] * aux[row,col]           (D_skip * xp)
// EPI 2: + bias[col] + aux[row,col]           (b_out + residual)
template<int BM, int BN, int BK, int TM, int TN, int EPI>
__global__ __launch_bounds__(256)
void sgemm(int M, int N, int K,
           const float* __restrict__ A, const float* __restrict__ B,
           float* __restrict__ C,
           const float* __restrict__ bias, const float* __restrict__ aux) {
    constexpr int NT = (BM / TM) * (BN / TN);   // 256
    __shared__ float As[BK][BM];
    __shared__ float Bs[BK][BN];
    const int tid  = threadIdx.x;
    const int tx   = tid % (BN / TN);
    const int ty   = tid / (BN / TN);
    const int brow = blockIdx.y;
    const int bcol = blockIdx.x;

    float acc[TM][TN];
    #pragma unroll
    for (int i = 0; i < TM; i++)
        #pragma unroll
        for (int j = 0; j < TN; j++) acc[i][j] = 0.0f;

    const float* Ab = A + (size_t)brow * BM * K;
    const float* Bb = B + (size_t)bcol * BN;

    for (int k0 = 0; k0 < K; k0 += BK) {
        // load A tile (transposed into As[k][m])
        #pragma unroll
        for (int i = tid; i < BM * BK / 4; i += NT) {
            int r  = i / (BK / 4);
            int cv = i % (BK / 4);
            float4 v = *reinterpret_cast<const float4*>(Ab + (size_t)r * K + k0 + cv * 4);
            As[cv * 4 + 0][r] = v.x;
            As[cv * 4 + 1][r] = v.y;
            As[cv * 4 + 2][r] = v.z;
            As[cv * 4 + 3][r] = v.w;
        }
        // load B tile
        #pragma unroll
        for (int i = tid; i < BK * BN / 4; i += NT) {
            int r  = i / (BN / 4);
            int cv = i % (BN / 4);
            *reinterpret_cast<float4*>(&Bs[r][cv * 4]) =
                *reinterpret_cast<const float4*>(Bb + (size_t)(k0 + r) * N + cv * 4);
        }
        __syncthreads();
        #pragma unroll
        for (int k = 0; k < BK; k++) {
            float ra[TM], rb[TN];
            #pragma unroll
            for (int i = 0; i < TM; i++) ra[i] = As[k][ty * TM + i];
            #pragma unroll
            for (int j = 0; j < TN; j++) rb[j] = Bs[k][tx * TN + j];
            #pragma unroll
            for (int i = 0; i < TM; i++)
                #pragma unroll
                for (int j = 0; j < TN; j++)
                    acc[i][j] = fmaf(ra[i], rb[j], acc[i][j]);
        }
        __syncthreads();
    }

    #pragma unroll
    for (int i = 0; i < TM; i++) {
        int row = brow * BM + ty * TM + i;
        #pragma unroll
        for (int j = 0; j < TN; j++) {
            int col = bcol * BN + tx * TN + j;
            float v = acc[i][j];
            size_t off = (size_t)row * N + col;
            if (EPI == 0) v += bias[col];
            if (EPI == 1) v += bias[col] * aux[off];
            if (EPI == 2) v += bias[col] + aux[off];
            C[off] = v;
        }
    }
}

// ---------------- chunked SSM scan ----------------
// Pass A: per (batch,chunk,n) compute chunk-local h_end with h_in = 0
__global__ void scan_passA(const float* __restrict__ A_log) {
    int b = blockIdx.x >> 4;
    int c = blockIdx.x & 15;
    int n = threadIdx.x;            // 0..63
    float ea = expf(A_log[n]);
    float Ab = expf(-ea);
    const float* base = g_bcx + (size_t)(b * SEQ + c * CHUNK) * 192;
    float h = 0.0f;
    #pragma unroll 8
    for (int t = 0; t < CHUNK; t++) {
        float Bv = base[(size_t)t * 192 + n];
        float xv = base[(size_t)t * 192 + 128 + n];
        h = fmaf(Ab, h, Bv * xv);
    }
    g_chunkend[(b * NCHUNK + c) * NSTATE + n] = h;
}

// Pass B: sequential chunk combine (1 block, 512 threads)
__global__ void scan_passB(const float* __restrict__ A_log) {
    int idx = threadIdx.x;          // 0..511
    int b = idx / NSTATE;
    int n = idx % NSTATE;
    float ea = expf(A_log[n]);
    float AL = expf(-(float)CHUNK * ea);   // A_bar^CHUNK
    float h = 0.0f;
    for (int c = 0; c < NCHUNK; c++) {
        g_hinit[(b * NCHUNK + c) * NSTATE + n] = h;
        h = fmaf(AL, h, g_chunkend[(b * NCHUNK + c) * NSTATE + n]);
    }
}

// Pass C: rescan with correct initial state, emit ch = C * h
__global__ void scan_passC(const float* __restrict__ A_log) {
    int b = blockIdx.x >> 4;
    int c = blockIdx.x & 15;
    int n = threadIdx.x;
    float ea = expf(A_log[n]);
    float Ab = expf(-ea);
    const float* base = g_bcx + (size_t)(b * SEQ + c * CHUNK) * 192;
    float* out = g_ch + (size_t)(b * SEQ + c * CHUNK) * NSTATE;
    float h = g_hinit[(b * NCHUNK + c) * NSTATE + n];
    #pragma unroll 8
    for (int t = 0; t < CHUNK; t++) {
        float Bv = base[(size_t)t * 192 + n];
        float Cv = base[(size_t)t * 192 + 64 + n];
        float xv = base[(size_t)t * 192 + 128 + n];
        h = fmaf(Ab, h, Bv * xv);
        out[(size_t)t * NSTATE + n] = Cv * h;
    }
}

// ---------------- launch ----------------
extern "C" void kernel_launch(void* const* d_in, const int* in_sizes, int n_in,
                              void* d_out, int out_size) {
    const float* x        = (const float*)d_in[0];
    const float* ln_gamma = (const float*)d_in[1];
    const float* ln_beta  = (const float*)d_in[2];
    const float* W_in     = (const float*)d_in[3];
    const float* b_in     = (const float*)d_in[4];
    const float* W_xs     = (const float*)d_in[5];
    const float* W_B      = (const float*)d_in[6];
    const float* b_B      = (const float*)d_in[7];
    const float* W_C      = (const float*)d_in[8];
    const float* b_C      = (const float*)d_in[9];
    const float* A_log    = (const float*)d_in[10];
    const float* D_skip   = (const float*)d_in[11];
    const float* W_so     = (const float*)d_in[12];
    const float* W_out    = (const float*)d_in[13];
    const float* b_out    = (const float*)d_in[14];
    float* out = (float*)d_out;

    float* xn  = nullptr; cudaGetSymbolAddress((void**)&xn,  g_xn);
    float* xp  = nullptr; cudaGetSymbolAddress((void**)&xp,  g_xp);
    float* bcx = nullptr; cudaGetSymbolAddress((void**)&bcx, g_bcx);
    float* ch  = nullptr; cudaGetSymbolAddress((void**)&ch,  g_ch);
    float* y1  = nullptr; cudaGetSymbolAddress((void**)&y1,  g_y1);
    float* Wcat = nullptr; cudaGetSymbolAddress((void**)&Wcat, g_Wcat);
    float* bcat = nullptr; cudaGetSymbolAddress((void**)&bcat, g_bcat);

    // 1) pack selective-projection weights
    pack_kernel<<<(DMODEL * 192 + 255) / 256, 256>>>(W_xs, W_B, b_B, W_C, b_C);

    // 2) LayerNorm
    ln_kernel<<<TOKENS, 128>>>(x, ln_gamma, ln_beta);

    // 3) xp = xn @ W_in + b_in          [32768,512]x[512,512]
    sgemm<128, 128, 8, 8, 8, 0><<<dim3(DMODEL / 128, TOKENS / 128), 256>>>(
        TOKENS, DMODEL, DMODEL, xn, W_in, xp, b_in, nullptr);

    // 4) [B|C|xs] = xp @ Wcat + bcat    [32768,512]x[512,192]
    sgemm<128, 64, 8, 8, 4, 0><<<dim3(192 / 64, TOKENS / 128), 256>>>(
        TOKENS, 192, DMODEL, xp, Wcat, bcx, bcat, nullptr);

    // 5) chunked scan -> ch = C * h
    scan_passA<<<BATCH * NCHUNK, NSTATE>>>(A_log);
    scan_passB<<<1, BATCH * NSTATE>>>(A_log);
    scan_passC<<<BATCH * NCHUNK, NSTATE>>>(A_log);

    // 6) y1 = ch @ W_so + D_skip * xp   [32768,64]x[64,512]
    sgemm<128, 128, 8, 8, 8, 1><<<dim3(DMODEL / 128, TOKENS / 128), 256>>>(
        TOKENS, DMODEL, NSTATE, ch, W_so, y1, D_skip, xp);

    // 7) out = y1 @ W_out + b_out + x   [32768,512]x[512,512]
    sgemm<128, 128, 8, 8, 8, 2><<<dim3(DMODEL / 128, TOKENS / 128), 256>>>(
        TOKENS, DMODEL, DMODEL, y1, W_out, out, b_out, x);
}

// round 3
// speedup vs baseline: 2.5976x; 2.5976x over previous
#include <cuda_runtime.h>
#include <cstdint>
#include <math.h>

// Problem constants
#define BATCH 8
#define SEQ   4096
#define DMODEL 512
#define NSTATE 64
#define TOKENS (BATCH*SEQ)          // 32768
#define NCHUNKS 16
#define CHUNK  (SEQ/NCHUNKS)        // 256
#define LN_EPS 1e-3f

// ---------------- device scratch ----------------
__device__ float g_xn [ (size_t)TOKENS * DMODEL ];
__device__ float g_xp [ (size_t)TOKENS * DMODEL ];
__device__ float g_bcx[ (size_t)TOKENS * 192 ];
__device__ float g_ch [ (size_t)TOKENS * NSTATE ];
__device__ float g_y1 [ (size_t)TOKENS * DMODEL ];
__device__ float g_WTin [ DMODEL * DMODEL ];   // [N,K] = W_in^T
__device__ float g_WTcat[ 192 * DMODEL ];      // [N,K] rows: B|C|xs
__device__ float g_WTso [ DMODEL * NSTATE ];   // [N(d),K(state)]
__device__ float g_WTout[ DMODEL * DMODEL ];
__device__ float g_bcat [ 192 ];
__device__ float g_chunkend[ BATCH * NCHUNKS * NSTATE ];
__device__ float g_hinit   [ BATCH * NCHUNKS * NSTATE ];

// ---------------- PTX helpers ----------------
__device__ __forceinline__ uint32_t smem_u32(const void* p) {
    uint32_t a;
    asm("{ .reg .u64 t; cvta.to.shared.u64 t, %1; cvt.u32.u64 %0, t; }" : "=r"(a) : "l"(p));
    return a;
}
__device__ __forceinline__ void cp16(uint32_t dst, const void* src) {
    asm volatile("cp.async.cg.shared.global [%0], [%1], 16;" :: "r"(dst), "l"(src));
}
#define CP_COMMIT()  asm volatile("cp.async.commit_group;" ::: "memory")
#define CP_WAIT1()   asm volatile("cp.async.wait_group 1;" ::: "memory")

__device__ __forceinline__ uint32_t f2tf32(float f) {
    uint32_t r;
    asm("cvt.rna.tf32.f32 %0, %1;" : "=r"(r) : "f"(f));
    return r;
}
__device__ __forceinline__ void mma8(float* d, uint32_t a0, uint32_t a1, uint32_t a2,
                                     uint32_t a3, uint32_t b0, uint32_t b1) {
    asm volatile(
        "mma.sync.aligned.m16n8k8.row.col.f32.tf32.tf32.f32 "
        "{%0,%1,%2,%3}, {%4,%5,%6,%7}, {%8,%9}, {%0,%1,%2,%3};"
        : "+f"(d[0]), "+f"(d[1]), "+f"(d[2]), "+f"(d[3])
        : "r"(a0), "r"(a1), "r"(a2), "r"(a3), "r"(b0), "r"(b1));
}

// ---------------- tf32 mma.sync GEMM ----------------
// C[M, N] = A[M, K] @ BT[:, K]^T + epilogue; CTA tile BM=128 x BN, BK=32, 3-stage cp.async
// EPI 0: + bias[col]
// EPI 1: + bias[col] * aux[row,col]
// EPI 2: + bias[col] + aux[row,col]
template<int BN, int EPI>
__global__ void __launch_bounds__(256, 2)
mma_gemm(const float* __restrict__ A, const float* __restrict__ BT,
         float* __restrict__ C, const float* __restrict__ bias,
         const float* __restrict__ aux, int K, int N) {
    constexpr int BM = 128, BK = 32, ST = 3, PAD = 36;
    constexpr int WN = BN / 4;       // warp tile N
    constexpr int NT = WN / 8;       // n-subtiles per warp
    extern __shared__ float smf[];
    float* As = smf;                       // ST * BM * PAD
    float* Bs = smf + ST * BM * PAD;       // ST * BN * PAD

    const int tid  = threadIdx.x;
    const int lane = tid & 31;
    const int wid  = tid >> 5;
    const int wm   = wid & 1;        // warp row (0..1) -> 64 rows each
    const int wn   = wid >> 1;       // warp col (0..3) -> WN cols each
    const int g    = lane >> 2;
    const int t    = lane & 3;
    const int m0   = blockIdx.y * BM;
    const int n0   = blockIdx.x * BN;
    const int S    = K / BK;

    const uint32_t asu = smem_u32(As);
    const uint32_t bsu = smem_u32(Bs);

    auto load_stage = [&](int s) {
        int buf = s % ST;
        uint32_t dA = asu + buf * BM * PAD * 4;
        uint32_t dB = bsu + buf * BN * PAD * 4;
        int k0 = s * BK;
        #pragma unroll
        for (int it = 0; it < 4; it++) {
            int i = tid + it * 256;          // 0..1023
            int row = i >> 3, c = i & 7;
            cp16(dA + row * PAD * 4 + c * 16,
                 A + (size_t)(m0 + row) * K + k0 + c * 4);
        }
        #pragma unroll
        for (int it = 0; it < BN / 32; it++) {
            int i = tid + it * 256;
            int row = i >> 3, c = i & 7;
            cp16(dB + row * PAD * 4 + c * 16,
                 BT + (size_t)(n0 + row) * K + k0 + c * 4);
        }
        CP_COMMIT();
    };

    float d[4][NT][4];
    #pragma unroll
    for (int mt = 0; mt < 4; mt++)
        #pragma unroll
        for (int nt = 0; nt < NT; nt++)
            #pragma unroll
            for (int j = 0; j < 4; j++) d[mt][nt][j] = 0.0f;

    load_stage(0);
    load_stage(1);

    for (int s = 0; s < S; s++) {
        CP_WAIT1();
        __syncthreads();
        if (s + 2 < S) load_stage(s + 2); else CP_COMMIT();

        int buf = s % ST;
        const float* ap = As + buf * BM * PAD + (wm * 64 + g) * PAD + t;
        const float* bp = Bs + buf * BN * PAD + (wn * WN + g) * PAD + t;
        #pragma unroll
        for (int kk = 0; kk < 4; kk++) {
            int ko = kk * 8;
            uint32_t af[4][4];
            #pragma unroll
            for (int mt = 0; mt < 4; mt++) {
                af[mt][0] = f2tf32(ap[(mt * 16    ) * PAD + ko    ]);
                af[mt][1] = f2tf32(ap[(mt * 16 + 8) * PAD + ko    ]);
                af[mt][2] = f2tf32(ap[(mt * 16    ) * PAD + ko + 4]);
                af[mt][3] = f2tf32(ap[(mt * 16 + 8) * PAD + ko + 4]);
            }
            uint32_t bf[NT][2];
            #pragma unroll
            for (int nt = 0; nt < NT; nt++) {
                bf[nt][0] = f2tf32(bp[nt * 8 * PAD + ko    ]);
                bf[nt][1] = f2tf32(bp[nt * 8 * PAD + ko + 4]);
            }
            #pragma unroll
            for (int mt = 0; mt < 4; mt++)
                #pragma unroll
                for (int nt = 0; nt < NT; nt++)
                    mma8(d[mt][nt], af[mt][0], af[mt][1], af[mt][2], af[mt][3],
                         bf[nt][0], bf[nt][1]);
        }
    }

    // ---- epilogue ----
    #pragma unroll
    for (int mt = 0; mt < 4; mt++) {
        int row = m0 + wm * 64 + mt * 16 + g;
        #pragma unroll
        for (int nt = 0; nt < NT; nt++) {
            int col = n0 + wn * WN + nt * 8 + 2 * t;
            float2 b2 = *reinterpret_cast<const float2*>(bias + col);
            size_t off0 = (size_t)row * N + col;
            size_t off1 = (size_t)(row + 8) * N + col;
            float2 v0 = make_float2(d[mt][nt][0], d[mt][nt][1]);
            float2 v1 = make_float2(d[mt][nt][2], d[mt][nt][3]);
            if (EPI == 0) {
                v0.x += b2.x; v0.y += b2.y;
                v1.x += b2.x; v1.y += b2.y;
            } else if (EPI == 1) {
                float2 a0 = *reinterpret_cast<const float2*>(aux + off0);
                float2 a1 = *reinterpret_cast<const float2*>(aux + off1);
                v0.x += b2.x * a0.x; v0.y += b2.y * a0.y;
                v1.x += b2.x * a1.x; v1.y += b2.y * a1.y;
            } else {
                float2 a0 = *reinterpret_cast<const float2*>(aux + off0);
                float2 a1 = *reinterpret_cast<const float2*>(aux + off1);
                v0.x += b2.x + a0.x; v0.y += b2.y + a0.y;
                v1.x += b2.x + a1.x; v1.y += b2.y + a1.y;
            }
            *reinterpret_cast<float2*>(C + off0) = v0;
            *reinterpret_cast<float2*>(C + off1) = v1;
        }
    }
}

// ---------------- weight prep: transposes + concat ----------------
__global__ void prep_weights(const float* __restrict__ W_in, const float* __restrict__ W_out,
                             const float* __restrict__ W_B, const float* __restrict__ W_C,
                             const float* __restrict__ W_xs, const float* __restrict__ W_so,
                             const float* __restrict__ b_B, const float* __restrict__ b_C) {
    int idx = blockIdx.x * 256 + threadIdx.x;
    if (idx < DMODEL * DMODEL) {
        int n = idx >> 9, k = idx & 511;
        g_WTin [idx] = W_in [k * DMODEL + n];
        g_WTout[idx] = W_out[k * DMODEL + n];
    }
    if (idx < 192 * DMODEL) {
        int n = idx >> 9, k = idx & 511;
        float v;
        if (n < 64)       v = W_B [k * 64 + n];
        else if (n < 128) v = W_C [k * 64 + (n - 64)];
        else              v = W_xs[k * 64 + (n - 128)];
        g_WTcat[idx] = v;
    }
    if (idx < DMODEL * NSTATE) {
        int d = idx >> 6, s = idx & 63;
        g_WTso[idx] = W_so[s * DMODEL + d];
    }
    if (idx < 192) g_bcat[idx] = (idx < 64) ? b_B[idx] : (idx < 128 ? b_C[idx - 64] : 0.0f);
}

// ---------------- LayerNorm ----------------
__global__ void ln_kernel(const float* __restrict__ x,
                          const float* __restrict__ gamma,
                          const float* __restrict__ beta) {
    int row = blockIdx.x;
    const float4* xr = reinterpret_cast<const float4*>(x) + (size_t)row * 128;
    int t = threadIdx.x;
    float4 v = xr[t];
    float s = v.x + v.y + v.z + v.w;
    float q = v.x*v.x + v.y*v.y + v.z*v.z + v.w*v.w;
    #pragma unroll
    for (int o = 16; o; o >>= 1) {
        s += __shfl_xor_sync(0xffffffffu, s, o);
        q += __shfl_xor_sync(0xffffffffu, q, o);
    }
    __shared__ float ss[4], qq[4];
    int w = t >> 5, l = t & 31;
    if (l == 0) { ss[w] = s; qq[w] = q; }
    __syncthreads();
    s = ss[0] + ss[1] + ss[2] + ss[3];
    q = qq[0] + qq[1] + qq[2] + qq[3];
    float mu  = s * (1.0f / DMODEL);
    float var = q * (1.0f / DMODEL) - mu * mu;
    float inv = rsqrtf(var + LN_EPS);
    float4 gv = reinterpret_cast<const float4*>(gamma)[t];
    float4 bv = reinterpret_cast<const float4*>(beta)[t];
    float4 o;
    o.x = (v.x - mu) * inv * gv.x + bv.x;
    o.y = (v.y - mu) * inv * gv.y + bv.y;
    o.z = (v.z - mu) * inv * gv.z + bv.z;
    o.w = (v.w - mu) * inv * gv.w + bv.w;
    reinterpret_cast<float4*>(g_xn)[(size_t)row * 128 + t] = o;
}

// ---------------- chunked SSM scan ----------------
__global__ void scan_passA(const float* __restrict__ A_log) {
    int b = blockIdx.x >> 4;
    int c = blockIdx.x & 15;
    int n = threadIdx.x;
    float Ab = expf(-expf(A_log[n]));
    const float* base = g_bcx + (size_t)(b * SEQ + c * CHUNK) * 192;
    float h = 0.0f;
    #pragma unroll 8
    for (int t = 0; t < CHUNK; t++) {
        float Bv = base[(size_t)t * 192 + n];
        float xv = base[(size_t)t * 192 + 128 + n];
        h = fmaf(Ab, h, Bv * xv);
    }
    g_chunkend[(b * NCHUNKS + c) * NSTATE + n] = h;
}

__global__ void scan_passB(const float* __restrict__ A_log) {
    int idx = threadIdx.x;
    int b = idx / NSTATE;
    int n = idx % NSTATE;
    float AL = expf(-(float)CHUNK * expf(A_log[n]));
    float h = 0.0f;
    for (int c = 0; c < NCHUNKS; c++) {
        g_hinit[(b * NCHUNKS + c) * NSTATE + n] = h;
        h = fmaf(AL, h, g_chunkend[(b * NCHUNKS + c) * NSTATE + n]);
    }
}

__global__ void scan_passC(const float* __restrict__ A_log) {
    int b = blockIdx.x >> 4;
    int c = blockIdx.x & 15;
    int n = threadIdx.x;
    float Ab = expf(-expf(A_log[n]));
    const float* base = g_bcx + (size_t)(b * SEQ + c * CHUNK) * 192;
    float* out = g_ch + (size_t)(b * SEQ + c * CHUNK) * NSTATE;
    float h = g_hinit[(b * NCHUNKS + c) * NSTATE + n];
    #pragma unroll 8
    for (int t = 0; t < CHUNK; t++) {
        float Bv = base[(size_t)t * 192 + n];
        float Cv = base[(size_t)t * 192 + 64 + n];
        float xv = base[(size_t)t * 192 + 128 + n];
        h = fmaf(Ab, h, Bv * xv);
        out[(size_t)t * NSTATE + n] = Cv * h;
    }
}

// ---------------- launch ----------------
extern "C" void kernel_launch(void* const* d_in, const int* in_sizes, int n_in,
                              void* d_out, int out_size) {
    const float* x        = (const float*)d_in[0];
    const float* ln_gamma = (const float*)d_in[1];
    const float* ln_beta  = (const float*)d_in[2];
    const float* W_in     = (const float*)d_in[3];
    const float* b_in     = (const float*)d_in[4];
    const float* W_xs     = (const float*)d_in[5];
    const float* W_B      = (const float*)d_in[6];
    const float* b_B      = (const float*)d_in[7];
    const float* W_C      = (const float*)d_in[8];
    const float* b_C      = (const float*)d_in[9];
    const float* A_log    = (const float*)d_in[10];
    const float* D_skip   = (const float*)d_in[11];
    const float* W_so     = (const float*)d_in[12];
    const float* W_out    = (const float*)d_in[13];
    const float* b_out    = (const float*)d_in[14];
    float* out = (float*)d_out;

    float* xn;    cudaGetSymbolAddress((void**)&xn,    g_xn);
    float* xp;    cudaGetSymbolAddress((void**)&xp,    g_xp);
    float* bcx;   cudaGetSymbolAddress((void**)&bcx,   g_bcx);
    float* ch;    cudaGetSymbolAddress((void**)&ch,    g_ch);
    float* y1;    cudaGetSymbolAddress((void**)&y1,    g_y1);
    float* WTin;  cudaGetSymbolAddress((void**)&WTin,  g_WTin);
    float* WTcat; cudaGetSymbolAddress((void**)&WTcat, g_WTcat);
    float* WTso;  cudaGetSymbolAddress((void**)&WTso,  g_WTso);
    float* WTout; cudaGetSymbolAddress((void**)&WTout, g_WTout);
    float* bcat;  cudaGetSymbolAddress((void**)&bcat,  g_bcat);

    const int SMEM128 = 3 * (128 + 128) * 36 * 4;   // 110592
    const int SMEM64  = 3 * (128 +  64) * 36 * 4;   //  82944
    cudaFuncSetAttribute(mma_gemm<128, 0>, cudaFuncAttributeMaxDynamicSharedMemorySize, SMEM128);
    cudaFuncSetAttribute(mma_gemm<128, 1>, cudaFuncAttributeMaxDynamicSharedMemorySize, SMEM128);
    cudaFuncSetAttribute(mma_gemm<128, 2>, cudaFuncAttributeMaxDynamicSharedMemorySize, SMEM128);
    cudaFuncSetAttribute(mma_gemm<64, 0>,  cudaFuncAttributeMaxDynamicSharedMemorySize, SMEM64);

    // 1) weight prep (transposes + concat)
    prep_weights<<<(DMODEL * DMODEL + 255) / 256, 256>>>(W_in, W_out, W_B, W_C, W_xs, W_so, b_B, b_C);

    // 2) LayerNorm
    ln_kernel<<<TOKENS, 128>>>(x, ln_gamma, ln_beta);

    // 3) xp = xn @ W_in + b_in          [32768,512]x[512,512]
    mma_gemm<128, 0><<<dim3(4, 256), 256, SMEM128>>>(xn, WTin, xp, b_in, nullptr, DMODEL, DMODEL);

    // 4) [B|C|xs] = xp @ Wcat + bcat    [32768,512]x[512,192]
    mma_gemm<64, 0><<<dim3(3, 256), 256, SMEM64>>>(xp, WTcat, bcx, bcat, nullptr, DMODEL, 192);

    // 5) chunked scan -> ch = C * h
    scan_passA<<<BATCH * NCHUNKS, NSTATE>>>(A_log);
    scan_passB<<<1, BATCH * NSTATE>>>(A_log);
    scan_passC<<<BATCH * NCHUNKS, NSTATE>>>(A_log);

    // 6) y1 = ch @ W_so + D_skip * xp   [32768,64]x[64,512]
    mma_gemm<128, 1><<<dim3(4, 256), 256, SMEM128>>>(ch, WTso, y1, D_skip, xp, NSTATE, DMODEL);

    // 7) out = y1 @ W_out + b_out + x   [32768,512]x[512,512]
    mma_gemm<128, 2><<<dim3(4, 256), 256, SMEM128>>>(y1, WTout, out, b_out, x, DMODEL, DMODEL);
}